// round 10
// baseline (speedup 1.0000x reference)
#include <cuda_runtime.h>

#define RANK 53
#define RPAD 64           // rank padded to 4 warps * 16
#define CIN  32
#define COUT 64
#define DIM  56
#define NVOX (56*56*56)   // 175616
#define STRH (56*56)
#define STRW 56
#define TH 8
#define TW 8
#define VOXT 128
#define NT   (NVOX / VOXT) // 1372

__device__ float g_bufA[RANK * NVOX];
__device__ float g_bufB[RANK * NVOX];

typedef unsigned long long ull;

__device__ __forceinline__ ull pk2(float lo, float hi) {
    ull r; asm("mov.b64 %0, {%1, %2};" : "=l"(r) : "f"(lo), "f"(hi)); return r;
}
__device__ __forceinline__ ull fma2(ull a, ull b, ull c) {
    ull d; asm("fma.rn.f32x2 %0, %1, %2, %3;" : "=l"(d) : "l"(a), "l"(b), "l"(c)); return d;
}
__device__ __forceinline__ void cpa16(float* smem_dst, const float* gsrc) {
    unsigned s = (unsigned)__cvta_generic_to_shared(smem_dst);
    asm volatile("cp.async.cg.shared.global [%0], [%1], 16;" :: "r"(s), "l"(gsrc));
}
#define CPA_COMMIT() asm volatile("cp.async.commit_group;" ::: "memory")
#define CPA_WAIT1()  asm volatile("cp.async.wait_group 1;"  ::: "memory")

// ---------- Kernel 1: pointwise Cin -> RANK (persistent, cp.async, 16r x 4v) ----------
// Warp w -> ranks [16w,16w+16) (broadcast weight LDS); lane -> 4 voxels.
// Per c-iter: 9 LDS.128 : 32 FFMA2 -> fma pipe binds.
__global__ __launch_bounds__(128, 4)
void k_pointwise(const float* __restrict__ x, const float* __restrict__ Ucin) {
    __shared__ float x_s[2][CIN * VOXT];     // 32 KB
    __shared__ ull   w_s[CIN * RPAD];        // 16 KB  (total 48 KB)

    const int tid = threadIdx.x;
    const int GRID = gridDim.x;

    int t = blockIdx.x;
    if (t < NT)
        for (int i = tid; i < CIN * 32; i += 128) {
            int c = i >> 5, q = i & 31;
            cpa16(x_s[0] + c * VOXT + q * 4, x + (size_t)c * NVOX + t * VOXT + q * 4);
        }
    CPA_COMMIT();

    for (int i = tid; i < CIN * RPAD; i += 128) {
        int c = i >> 6, r = i & 63;
        float v = (r < RANK) ? Ucin[c * RANK + r] : 0.f;
        w_s[i] = pk2(v, v);
    }

    if (t + GRID < NT)
        for (int i = tid; i < CIN * 32; i += 128) {
            int c = i >> 5, q = i & 31;
            cpa16(x_s[1] + c * VOXT + q * 4, x + (size_t)c * NVOX + (t + GRID) * VOXT + q * 4);
        }
    CPA_COMMIT();

    const int warp = tid >> 5;
    const int lane = tid & 31;
    const int r0 = warp * 16;
    const int v0 = lane * 4;

    int p = 0;
    for (; t < NT; t += GRID, p ^= 1) {
        CPA_WAIT1();
        __syncthreads();
        const float* xs = x_s[p];

        ull acc[16][2];
#pragma unroll
        for (int i = 0; i < 16; i++) { acc[i][0] = 0ull; acc[i][1] = 0ull; }

        const ull* wp = w_s + r0;
        const float* xp = xs + v0;
        for (int c = 0; c < CIN; c++, wp += RPAD, xp += VOXT) {
            ulonglong2 wv[8];
#pragma unroll
            for (int k = 0; k < 8; k++) wv[k] = *(const ulonglong2*)(wp + 2 * k);
            ulonglong2 xa = *(const ulonglong2*)(xp);
#pragma unroll
            for (int k = 0; k < 8; k++) {
                acc[2*k  ][0] = fma2(wv[k].x, xa.x, acc[2*k  ][0]);
                acc[2*k  ][1] = fma2(wv[k].x, xa.y, acc[2*k  ][1]);
                acc[2*k+1][0] = fma2(wv[k].y, xa.x, acc[2*k+1][0]);
                acc[2*k+1][1] = fma2(wv[k].y, xa.y, acc[2*k+1][1]);
            }
        }

#pragma unroll
        for (int i = 0; i < 16; i++) {
            int r = r0 + i;
            if (r < RANK)
                *(ulonglong2*)(g_bufA + (size_t)r * NVOX + t * VOXT + v0) =
                    make_ulonglong2(acc[i][0], acc[i][1]);
        }
        __syncthreads();

        int tn = t + 2 * GRID;
        if (tn < NT)
            for (int i = tid; i < CIN * 32; i += 128) {
                int c = i >> 5, q = i & 31;
                cpa16(x_s[p] + c * VOXT + q * 4, x + (size_t)c * NVOX + tn * VOXT + q * 4);
            }
        CPA_COMMIT();
    }
}

// ---------- Kernel 2: full separable 3D conv (H, W, then D) per rank ----------
__global__ __launch_bounds__(256)
void k_convHWD(const float* __restrict__ in, float* __restrict__ out,
               const float* __restrict__ Ukh, const float* __restrict__ Ukw,
               const float* __restrict__ Ukd) {
    __shared__ float s [(TH + 2) * (TW + 2) * DIM];   // 22.4 KB
    __shared__ float s2[TH * TW * DIM];               // 14.3 KB

    int r  = blockIdx.z;
    int h0 = blockIdx.y * TH;
    int w0 = blockIdx.x * TW;
    const float* base = in + (size_t)r * NVOX;

    const int NLOAD4 = (TH + 2) * (TW + 2) * (DIM / 4);
    for (int i = threadIdx.x; i < NLOAD4; i += 256) {
        int dq = i % (DIM / 4);
        int t  = i / (DIM / 4);
        int lw = t % (TW + 2);
        int lh = t / (TW + 2);
        int gh = h0 + lh - 1, gw = w0 + lw - 1;
        float4 val = make_float4(0.f, 0.f, 0.f, 0.f);
        if (gh >= 0 && gh < DIM && gw >= 0 && gw < DIM)
            val = *(const float4*)(base + gh * STRH + gw * STRW + dq * 4);
        *(float4*)(s + (lh * (TW + 2) + lw) * DIM + dq * 4) = val;
    }
    __syncthreads();

    float kh[3] = {Ukh[r], Ukh[RANK + r], Ukh[2 * RANK + r]};
    float kw[3] = {Ukw[r], Ukw[RANK + r], Ukw[2 * RANK + r]};
    float kd[3] = {Ukd[r], Ukd[RANK + r], Ukd[2 * RANK + r]};
    float kk[9];
#pragma unroll
    for (int i = 0; i < 3; i++)
#pragma unroll
        for (int j = 0; j < 3; j++) kk[i * 3 + j] = kh[i] * kw[j];

    const int NOUT4 = TH * TW * (DIM / 4);   // 896
    for (int o = threadIdx.x; o < NOUT4; o += 256) {
        int dq = o % (DIM / 4);
        int t  = o / (DIM / 4);
        int lw = t % TW;
        int lh = t / TW;
        float4 acc = make_float4(0.f, 0.f, 0.f, 0.f);
#pragma unroll
        for (int i = 0; i < 3; i++)
#pragma unroll
            for (int j = 0; j < 3; j++) {
                const float4 v = *(const float4*)(s + ((lh + i) * (TW + 2) + (lw + j)) * DIM + dq * 4);
                float c = kk[i * 3 + j];
                acc.x += c * v.x; acc.y += c * v.y;
                acc.z += c * v.z; acc.w += c * v.w;
            }
        *(float4*)(s2 + (lh * TW + lw) * DIM + dq * 4) = acc;
    }
    __syncthreads();

    float* obase = out + (size_t)r * NVOX;
    for (int o = threadIdx.x; o < NOUT4; o += 256) {
        int dq = o % (DIM / 4);
        int t  = o / (DIM / 4);
        int lw = t % TW;
        int lh = t / TW;
        const float* line = s2 + (lh * TW + lw) * DIM;
        int z = dq * 4;
        float4 c = *(const float4*)(line + z);
        float lf = (z > 0)  ? line[z - 1] : 0.f;
        float rt = (z < 52) ? line[z + 4] : 0.f;
        float4 oq;
        oq.x = kd[0] * lf  + kd[1] * c.x + kd[2] * c.y;
        oq.y = kd[0] * c.x + kd[1] * c.y + kd[2] * c.z;
        oq.z = kd[0] * c.y + kd[1] * c.z + kd[2] * c.w;
        oq.w = kd[0] * c.z + kd[1] * c.w + kd[2] * rt;
        *(float4*)(obase + (h0 + lh) * STRH + (w0 + lw) * STRW + z) = oq;
    }
}

// ---------- Kernel 3: pure GEMM RANK -> 64 + bias (persistent, 16c x 4v) ----------
// Dynamic smem: t_s[2][53*128]f [0,54272); w_s ull[53*64] [54272,81408); b_s f[64] [81408,81664)
#define DPROJ_SMEM 81664
__global__ __launch_bounds__(128, 2)
void k_dproj(const float* __restrict__ in, const float* __restrict__ Ucout,
             const float* __restrict__ bias, float* __restrict__ out) {
    extern __shared__ char dsm[];
    float* t_s[2] = {(float*)dsm, (float*)(dsm + 27136)};
    ull*   w_s = (ull*)(dsm + 54272);
    float* b_s = (float*)(dsm + 81408);

    const int tid = threadIdx.x;
    const int GRID = gridDim.x;

    int t = blockIdx.x;
    if (t < NT)
        for (int i = tid; i < RANK * 32; i += 128) {
            int r = i >> 5, q = i & 31;
            cpa16(t_s[0] + r * VOXT + q * 4, in + (size_t)r * NVOX + t * VOXT + q * 4);
        }
    CPA_COMMIT();

    for (int i = tid; i < RANK * COUT; i += 128) {
        float v = Ucout[i];
        w_s[i] = pk2(v, v);
    }
    if (tid < COUT) b_s[tid] = bias[tid];

    if (t + GRID < NT)
        for (int i = tid; i < RANK * 32; i += 128) {
            int r = i >> 5, q = i & 31;
            cpa16(t_s[1] + r * VOXT + q * 4, in + (size_t)r * NVOX + (t + GRID) * VOXT + q * 4);
        }
    CPA_COMMIT();

    const int warp = tid >> 5;
    const int lane = tid & 31;
    const int j0 = warp * 16;
    const int v0 = lane * 4;

    int p = 0;
    for (; t < NT; t += GRID, p ^= 1) {
        CPA_WAIT1();
        __syncthreads();
        const float* ts = t_s[p];

        ull acc[16][2];
#pragma unroll
        for (int i = 0; i < 16; i++) { acc[i][0] = 0ull; acc[i][1] = 0ull; }

        const ull* wp = w_s + j0;
        const float* tp = ts + v0;
        for (int r = 0; r < RANK; r++, wp += COUT, tp += VOXT) {
            ulonglong2 wv[8];
#pragma unroll
            for (int k = 0; k < 8; k++) wv[k] = *(const ulonglong2*)(wp + 2 * k);
            ulonglong2 ta = *(const ulonglong2*)(tp);
#pragma unroll
            for (int k = 0; k < 8; k++) {
                acc[2*k  ][0] = fma2(wv[k].x, ta.x, acc[2*k  ][0]);
                acc[2*k  ][1] = fma2(wv[k].x, ta.y, acc[2*k  ][1]);
                acc[2*k+1][0] = fma2(wv[k].y, ta.x, acc[2*k+1][0]);
                acc[2*k+1][1] = fma2(wv[k].y, ta.y, acc[2*k+1][1]);
            }
        }

        const ull one2 = pk2(1.f, 1.f);
#pragma unroll
        for (int i = 0; i < 16; i++) {
            int j = j0 + i;
            ull bb = pk2(b_s[j], b_s[j]);
            acc[i][0] = fma2(bb, one2, acc[i][0]);
            acc[i][1] = fma2(bb, one2, acc[i][1]);
            *(ulonglong2*)(out + (size_t)j * NVOX + t * VOXT + v0) =
                make_ulonglong2(acc[i][0], acc[i][1]);
        }
        __syncthreads();

        int tn = t + 2 * GRID;
        if (tn < NT)
            for (int i = tid; i < RANK * 32; i += 128) {
                int r = i >> 5, q = i & 31;
                cpa16(t_s[p] + r * VOXT + q * 4, in + (size_t)r * NVOX + tn * VOXT + q * 4);
            }
        CPA_COMMIT();
    }
}

extern "C" void kernel_launch(void* const* d_in, const int* in_sizes, int n_in,
                              void* d_out, int out_size) {
    const float* x     = (const float*)d_in[0];
    const float* Ukh   = (const float*)d_in[1];
    const float* Ukw   = (const float*)d_in[2];
    const float* Ukd   = (const float*)d_in[3];
    const float* Ucin  = (const float*)d_in[4];
    const float* Ucout = (const float*)d_in[5];
    const float* bias  = (const float*)d_in[6];
    float* out = (float*)d_out;

    float *bufA, *bufB;
    cudaGetSymbolAddress((void**)&bufA, g_bufA);
    cudaGetSymbolAddress((void**)&bufB, g_bufB);

    cudaFuncSetAttribute(k_dproj, cudaFuncAttributeMaxDynamicSharedMemorySize, DPROJ_SMEM);

    k_pointwise<<<592, 128>>>(x, Ucin);                    // 4 CTAs/SM, one wave
    dim3 g2(DIM / TW, DIM / TH, RANK);                     // 7 x 7 x 53
    k_convHWD<<<g2, 256>>>(bufA, bufB, Ukh, Ukw, Ukd);
    k_dproj<<<296, 128, DPROJ_SMEM>>>(bufB, Ucout, bias, out);  // 2 CTAs/SM, one wave
}

// round 11
// speedup vs baseline: 1.1447x; 1.1447x over previous
#include <cuda_runtime.h>

#define RANK 53
#define RPAD 56           // 7 warps * 8 ranks
#define CIN  32
#define COUT 64
#define DIM  56
#define NVOX (56*56*56)   // 175616
#define STRH (56*56)
#define STRW 56
#define TH 8
#define TW 8
#define VOXT 128
#define NT   (NVOX / VOXT) // 1372

__device__ float g_bufA[RANK * NVOX];
__device__ float g_bufB[RANK * NVOX];

typedef unsigned long long ull;

__device__ __forceinline__ ull pk2(float lo, float hi) {
    ull r; asm("mov.b64 %0, {%1, %2};" : "=l"(r) : "f"(lo), "f"(hi)); return r;
}
__device__ __forceinline__ ull fma2(ull a, ull b, ull c) {
    ull d; asm("fma.rn.f32x2 %0, %1, %2, %3;" : "=l"(d) : "l"(a), "l"(b), "l"(c)); return d;
}
__device__ __forceinline__ void cpa16(float* smem_dst, const float* gsrc) {
    unsigned s = (unsigned)__cvta_generic_to_shared(smem_dst);
    asm volatile("cp.async.cg.shared.global [%0], [%1], 16;" :: "r"(s), "l"(gsrc));
}
#define CPA_COMMIT() asm volatile("cp.async.commit_group;" ::: "memory")
#define CPA_WAIT1()  asm volatile("cp.async.wait_group 1;"  ::: "memory")

// ---------- Kernel 1: pointwise Cin -> RANK (persistent, cp.async, 8r x 4v) ----------
// Weights staged as floats; packed to (v,v) f32x2 via mov at use.
__global__ __launch_bounds__(224, 4)
void k_pointwise(const float* __restrict__ x, const float* __restrict__ Ucin) {
    __shared__ float x_s[2][CIN * VOXT];     // 32 KB
    __shared__ float w_s[CIN * RPAD];        // 7 KB

    const int tid = threadIdx.x;
    const int GRID = gridDim.x;

    int t = blockIdx.x;
    if (t < NT)
        for (int i = tid; i < CIN * 32; i += 224) {
            int c = i >> 5, q = i & 31;
            cpa16(x_s[0] + c * VOXT + q * 4, x + (size_t)c * NVOX + t * VOXT + q * 4);
        }
    CPA_COMMIT();

    for (int i = tid; i < CIN * RPAD; i += 224) {
        int c = i / RPAD, r = i % RPAD;
        w_s[i] = (r < RANK) ? Ucin[c * RANK + r] : 0.f;
    }

    if (t + GRID < NT)
        for (int i = tid; i < CIN * 32; i += 224) {
            int c = i >> 5, q = i & 31;
            cpa16(x_s[1] + c * VOXT + q * 4, x + (size_t)c * NVOX + (t + GRID) * VOXT + q * 4);
        }
    CPA_COMMIT();

    const int warp = tid >> 5;
    const int lane = tid & 31;
    const int r0 = warp * 8;
    const int v0 = lane * 4;

    int p = 0;
    for (; t < NT; t += GRID, p ^= 1) {
        CPA_WAIT1();
        __syncthreads();
        const float* xs = x_s[p];

        ull acc[8][2];
#pragma unroll
        for (int i = 0; i < 8; i++) { acc[i][0] = 0ull; acc[i][1] = 0ull; }

        const float* wp = w_s + r0;
        const float* xp = xs + v0;
        for (int c = 0; c < CIN; c++, wp += RPAD, xp += VOXT) {
            float4 wa = *(const float4*)(wp);
            float4 wb = *(const float4*)(wp + 4);
            ulonglong2 xa = *(const ulonglong2*)(xp);
            ull w[8];
            w[0] = pk2(wa.x, wa.x); w[1] = pk2(wa.y, wa.y);
            w[2] = pk2(wa.z, wa.z); w[3] = pk2(wa.w, wa.w);
            w[4] = pk2(wb.x, wb.x); w[5] = pk2(wb.y, wb.y);
            w[6] = pk2(wb.z, wb.z); w[7] = pk2(wb.w, wb.w);
#pragma unroll
            for (int i = 0; i < 8; i++) {
                acc[i][0] = fma2(w[i], xa.x, acc[i][0]);
                acc[i][1] = fma2(w[i], xa.y, acc[i][1]);
            }
        }

#pragma unroll
        for (int i = 0; i < 8; i++) {
            int r = r0 + i;
            if (r < RANK)
                *(ulonglong2*)(g_bufA + (size_t)r * NVOX + t * VOXT + v0) =
                    make_ulonglong2(acc[i][0], acc[i][1]);
        }
        __syncthreads();

        int tn = t + 2 * GRID;
        if (tn < NT)
            for (int i = tid; i < CIN * 32; i += 224) {
                int c = i >> 5, q = i & 31;
                cpa16(x_s[p] + c * VOXT + q * 4, x + (size_t)c * NVOX + tn * VOXT + q * 4);
            }
        CPA_COMMIT();
    }
}

// ---------- Kernel 2: full separable 3D conv (H, W, then D) per rank ----------
__global__ __launch_bounds__(256)
void k_convHWD(const float* __restrict__ in, float* __restrict__ out,
               const float* __restrict__ Ukh, const float* __restrict__ Ukw,
               const float* __restrict__ Ukd) {
    __shared__ float s [(TH + 2) * (TW + 2) * DIM];   // 22.4 KB
    __shared__ float s2[TH * TW * DIM];               // 14.3 KB

    int r  = blockIdx.z;
    int h0 = blockIdx.y * TH;
    int w0 = blockIdx.x * TW;
    const float* base = in + (size_t)r * NVOX;

    const int NLOAD4 = (TH + 2) * (TW + 2) * (DIM / 4);
    for (int i = threadIdx.x; i < NLOAD4; i += 256) {
        int dq = i % (DIM / 4);
        int t  = i / (DIM / 4);
        int lw = t % (TW + 2);
        int lh = t / (TW + 2);
        int gh = h0 + lh - 1, gw = w0 + lw - 1;
        float4 val = make_float4(0.f, 0.f, 0.f, 0.f);
        if (gh >= 0 && gh < DIM && gw >= 0 && gw < DIM)
            val = *(const float4*)(base + gh * STRH + gw * STRW + dq * 4);
        *(float4*)(s + (lh * (TW + 2) + lw) * DIM + dq * 4) = val;
    }
    __syncthreads();

    float kh[3] = {Ukh[r], Ukh[RANK + r], Ukh[2 * RANK + r]};
    float kw[3] = {Ukw[r], Ukw[RANK + r], Ukw[2 * RANK + r]};
    float kd[3] = {Ukd[r], Ukd[RANK + r], Ukd[2 * RANK + r]};
    float kk[9];
#pragma unroll
    for (int i = 0; i < 3; i++)
#pragma unroll
        for (int j = 0; j < 3; j++) kk[i * 3 + j] = kh[i] * kw[j];

    const int NOUT4 = TH * TW * (DIM / 4);   // 896
    for (int o = threadIdx.x; o < NOUT4; o += 256) {
        int dq = o % (DIM / 4);
        int t  = o / (DIM / 4);
        int lw = t % TW;
        int lh = t / TW;
        float4 acc = make_float4(0.f, 0.f, 0.f, 0.f);
#pragma unroll
        for (int i = 0; i < 3; i++)
#pragma unroll
            for (int j = 0; j < 3; j++) {
                const float4 v = *(const float4*)(s + ((lh + i) * (TW + 2) + (lw + j)) * DIM + dq * 4);
                float c = kk[i * 3 + j];
                acc.x += c * v.x; acc.y += c * v.y;
                acc.z += c * v.z; acc.w += c * v.w;
            }
        *(float4*)(s2 + (lh * TW + lw) * DIM + dq * 4) = acc;
    }
    __syncthreads();

    float* obase = out + (size_t)r * NVOX;
    for (int o = threadIdx.x; o < NOUT4; o += 256) {
        int dq = o % (DIM / 4);
        int t  = o / (DIM / 4);
        int lw = t % TW;
        int lh = t / TW;
        const float* line = s2 + (lh * TW + lw) * DIM;
        int z = dq * 4;
        float4 c = *(const float4*)(line + z);
        float lf = (z > 0)  ? line[z - 1] : 0.f;
        float rt = (z < 52) ? line[z + 4] : 0.f;
        float4 oq;
        oq.x = kd[0] * lf  + kd[1] * c.x + kd[2] * c.y;
        oq.y = kd[0] * c.x + kd[1] * c.y + kd[2] * c.z;
        oq.z = kd[0] * c.y + kd[1] * c.z + kd[2] * c.w;
        oq.w = kd[0] * c.z + kd[1] * c.w + kd[2] * rt;
        *(float4*)(obase + (h0 + lh) * STRH + (w0 + lw) * STRW + z) = oq;
    }
}

// ---------- Kernel 3: pure GEMM RANK -> 64 + bias (persistent, 8c x 4v, 3 CTAs/SM) ----------
// Dynamic smem: t_s[2][53*128]f [0,54272); w_s f[53*64] [54272,67840); b_s f[64] [67840,68096)
#define DPROJ_SMEM 68096
__global__ __launch_bounds__(256, 3)
void k_dproj(const float* __restrict__ in, const float* __restrict__ Ucout,
             const float* __restrict__ bias, float* __restrict__ out) {
    extern __shared__ char dsm[];
    float* t_s[2] = {(float*)dsm, (float*)(dsm + 27136)};
    float* w_s = (float*)(dsm + 54272);
    float* b_s = (float*)(dsm + 67840);

    const int tid = threadIdx.x;
    const int GRID = gridDim.x;

    int t = blockIdx.x;
    if (t < NT)
        for (int i = tid; i < RANK * 32; i += 256) {
            int r = i >> 5, q = i & 31;
            cpa16(t_s[0] + r * VOXT + q * 4, in + (size_t)r * NVOX + t * VOXT + q * 4);
        }
    CPA_COMMIT();

    for (int i = tid; i < RANK * COUT; i += 256) w_s[i] = Ucout[i];
    if (tid < COUT) b_s[tid] = bias[tid];

    if (t + GRID < NT)
        for (int i = tid; i < RANK * 32; i += 256) {
            int r = i >> 5, q = i & 31;
            cpa16(t_s[1] + r * VOXT + q * 4, in + (size_t)r * NVOX + (t + GRID) * VOXT + q * 4);
        }
    CPA_COMMIT();

    const int warp = tid >> 5;
    const int lane = tid & 31;
    const int j0 = warp * 8;
    const int v0 = lane * 4;

    int p = 0;
    for (; t < NT; t += GRID, p ^= 1) {
        CPA_WAIT1();
        __syncthreads();
        const float* ts = t_s[p];

        ull acc[8][2];
#pragma unroll
        for (int i = 0; i < 8; i++) { acc[i][0] = 0ull; acc[i][1] = 0ull; }

        const float* wp = w_s + j0;
        const float* tp = ts + v0;
        for (int r = 0; r < RANK; r++, wp += COUT, tp += VOXT) {
            float4 wa = *(const float4*)(wp);
            float4 wb = *(const float4*)(wp + 4);
            ulonglong2 ta = *(const ulonglong2*)(tp);
            ull w[8];
            w[0] = pk2(wa.x, wa.x); w[1] = pk2(wa.y, wa.y);
            w[2] = pk2(wa.z, wa.z); w[3] = pk2(wa.w, wa.w);
            w[4] = pk2(wb.x, wb.x); w[5] = pk2(wb.y, wb.y);
            w[6] = pk2(wb.z, wb.z); w[7] = pk2(wb.w, wb.w);
#pragma unroll
            for (int i = 0; i < 8; i++) {
                acc[i][0] = fma2(w[i], ta.x, acc[i][0]);
                acc[i][1] = fma2(w[i], ta.y, acc[i][1]);
            }
        }

        const ull one2 = pk2(1.f, 1.f);
#pragma unroll
        for (int i = 0; i < 8; i++) {
            int j = j0 + i;
            ull bb = pk2(b_s[j], b_s[j]);
            acc[i][0] = fma2(bb, one2, acc[i][0]);
            acc[i][1] = fma2(bb, one2, acc[i][1]);
            *(ulonglong2*)(out + (size_t)j * NVOX + t * VOXT + v0) =
                make_ulonglong2(acc[i][0], acc[i][1]);
        }
        __syncthreads();

        int tn = t + 2 * GRID;
        if (tn < NT)
            for (int i = tid; i < RANK * 32; i += 256) {
                int r = i >> 5, q = i & 31;
                cpa16(t_s[p] + r * VOXT + q * 4, in + (size_t)r * NVOX + tn * VOXT + q * 4);
            }
        CPA_COMMIT();
    }
}

extern "C" void kernel_launch(void* const* d_in, const int* in_sizes, int n_in,
                              void* d_out, int out_size) {
    const float* x     = (const float*)d_in[0];
    const float* Ukh   = (const float*)d_in[1];
    const float* Ukw   = (const float*)d_in[2];
    const float* Ukd   = (const float*)d_in[3];
    const float* Ucin  = (const float*)d_in[4];
    const float* Ucout = (const float*)d_in[5];
    const float* bias  = (const float*)d_in[6];
    float* out = (float*)d_out;

    float *bufA, *bufB;
    cudaGetSymbolAddress((void**)&bufA, g_bufA);
    cudaGetSymbolAddress((void**)&bufB, g_bufB);

    cudaFuncSetAttribute(k_dproj, cudaFuncAttributeMaxDynamicSharedMemorySize, DPROJ_SMEM);

    k_pointwise<<<592, 224>>>(x, Ucin);                    // 4 CTAs/SM, one wave
    dim3 g2(DIM / TW, DIM / TH, RANK);                     // 7 x 7 x 53
    k_convHWD<<<g2, 256>>>(bufA, bufB, Ukh, Ukw, Ukd);
    k_dproj<<<444, 256, DPROJ_SMEM>>>(bufB, Ucout, bias, out);  // 3 CTAs/SM, one wave
}